// round 5
// baseline (speedup 1.0000x reference)
#include <cuda_runtime.h>
#include <math.h>

#define B_   256
#define D_   256
#define H_   8
#define HD_  32
#define FF_  1024
#define M_   2048
#define SCALE_ 0.17677669529663687f   /* 1/sqrt(32) */
#define THR_ 0.5f
#define MOM_ 0.9f
#define LR_  0.1f
#define NSPLIT_ 16
#define KSPLIT_ (M_ / NSPLIT_)   /* 128 keys per split */
#define FSPLIT_ 16               /* FFN2 split-K */

// ---------------- scratch (device globals) -----------------------------------
__device__ float g_proj_src[B_ * 3 * D_];        // [B,768] q|k|v of src
__device__ float g_kv_mem[M_ * 2 * D_];          // [M,512] k|v of memory
__device__ float g_logits[H_ * B_ * M_];         // [H][B][M] logits -> probs
__device__ float g_pself[H_ * B_];
__device__ float g_ctx_part[NSPLIT_ * B_ * D_];  // AV split-K partials
__device__ float g_attn_part[4 * B_ * D_];       // out-proj split-K partials
__device__ float g_ff_part[FSPLIT_ * B_ * D_];   // FFN2 split-K partials
__device__ float g_blockmax[32 * B_];            // cosine per-(bn,row) maxima
__device__ float g_src_norm[B_];
__device__ float g_mem_norm[M_];
__device__ float g_mem_sq[M_];
__device__ float g_ctx[B_ * D_];
__device__ float g_h[B_ * D_];
__device__ float g_hidden[B_ * FF_];
__device__ int   g_row_src[M_];                  // mem row -> update source (or -1)
__device__ float g_upd_s[B_];

// ---------------- row norms --------------------------------------------------
__global__ void norms_kernel(const float* __restrict__ src, const float* __restrict__ mem) {
    int row = blockIdx.x * 8 + threadIdx.y;
    int lane = threadIdx.x;
    if (row >= B_ + M_) return;
    bool is_src = row < B_;
    const float* base = is_src ? (src + row * D_) : (mem + (row - B_) * D_);
    float s = 0.f;
    #pragma unroll
    for (int d = lane; d < D_; d += 32) { float v = base[d]; s += v * v; }
    #pragma unroll
    for (int o = 16; o; o >>= 1) s += __shfl_xor_sync(0xFFFFFFFFu, s, o);
    if (lane == 0) {
        float nv = fmaxf(sqrtf(s), 1e-8f);
        if (is_src) g_src_norm[row] = nv;
        else { g_mem_norm[row - B_] = nv; g_mem_sq[row - B_] = s; }
    }
}

// ---------------- SGEMM: C[.,N] = A @ B^T, 64x64 tile, 128 thr, 8x4 micro ----
template <int MODE>
__global__ void __launch_bounds__(128)
sgemm128(const float* __restrict__ A, const float* __restrict__ Bm,
         const float* __restrict__ bias, float* __restrict__ C,
         int K, int lda, int ldb, int ldc, int aB, int bB, int cB) {
    __shared__ float As[2][16][64];
    __shared__ float Bs[2][16][64];
    int tid = threadIdx.x;
    int tx = tid & 15, ty = tid >> 4;
    int r = tid & 63, half = tid >> 6;
    int h8 = half * 8;
    const float* Ap = A + (size_t)blockIdx.z * aB + (size_t)(blockIdx.y * 64 + r) * lda + h8;
    const float* Bp = Bm + (size_t)blockIdx.z * bB + (size_t)(blockIdx.x * 64 + r) * ldb + h8;

    float4 a0 = *(const float4*)(Ap);
    float4 a1 = *(const float4*)(Ap + 4);
    float4 b0 = *(const float4*)(Bp);
    float4 b1 = *(const float4*)(Bp + 4);
    As[0][h8 + 0][r] = a0.x; As[0][h8 + 1][r] = a0.y; As[0][h8 + 2][r] = a0.z; As[0][h8 + 3][r] = a0.w;
    As[0][h8 + 4][r] = a1.x; As[0][h8 + 5][r] = a1.y; As[0][h8 + 6][r] = a1.z; As[0][h8 + 7][r] = a1.w;
    Bs[0][h8 + 0][r] = b0.x; Bs[0][h8 + 1][r] = b0.y; Bs[0][h8 + 2][r] = b0.z; Bs[0][h8 + 3][r] = b0.w;
    Bs[0][h8 + 4][r] = b1.x; Bs[0][h8 + 5][r] = b1.y; Bs[0][h8 + 6][r] = b1.z; Bs[0][h8 + 7][r] = b1.w;
    __syncthreads();

    float acc[8][4] = {};
    int nIt = K >> 4;
    for (int it = 0; it < nIt; ++it) {
        int buf = it & 1;
        bool more = (it + 1) < nIt;
        if (more) {
            int k0 = (it + 1) << 4;
            a0 = *(const float4*)(Ap + k0);
            a1 = *(const float4*)(Ap + k0 + 4);
            b0 = *(const float4*)(Bp + k0);
            b1 = *(const float4*)(Bp + k0 + 4);
        }
        #pragma unroll
        for (int kk = 0; kk < 16; kk++) {
            float a[8], b[4];
            *(float4*)&a[0] = *(const float4*)&As[buf][kk][ty * 8];
            *(float4*)&a[4] = *(const float4*)&As[buf][kk][ty * 8 + 4];
            *(float4*)&b[0] = *(const float4*)&Bs[buf][kk][tx * 4];
            #pragma unroll
            for (int i = 0; i < 8; i++)
                #pragma unroll
                for (int j = 0; j < 4; j++) acc[i][j] += a[i] * b[j];
        }
        if (more) {
            int nb = buf ^ 1;
            As[nb][h8 + 0][r] = a0.x; As[nb][h8 + 1][r] = a0.y; As[nb][h8 + 2][r] = a0.z; As[nb][h8 + 3][r] = a0.w;
            As[nb][h8 + 4][r] = a1.x; As[nb][h8 + 5][r] = a1.y; As[nb][h8 + 6][r] = a1.z; As[nb][h8 + 7][r] = a1.w;
            Bs[nb][h8 + 0][r] = b0.x; Bs[nb][h8 + 1][r] = b0.y; Bs[nb][h8 + 2][r] = b0.z; Bs[nb][h8 + 3][r] = b0.w;
            Bs[nb][h8 + 4][r] = b1.x; Bs[nb][h8 + 5][r] = b1.y; Bs[nb][h8 + 6][r] = b1.z; Bs[nb][h8 + 7][r] = b1.w;
            __syncthreads();
        }
    }

    int row0 = blockIdx.y * 64 + ty * 8;
    int col0 = blockIdx.x * 64 + tx * 4;
    if (MODE == 1) {
        float inm[4];
        #pragma unroll
        for (int j = 0; j < 4; j++) inm[j] = 1.f / g_mem_norm[col0 + j];
        #pragma unroll
        for (int i = 0; i < 8; i++) {
            float ins = 1.f / g_src_norm[row0 + i];
            float mx = -1e30f;
            #pragma unroll
            for (int j = 0; j < 4; j++) mx = fmaxf(mx, acc[i][j] * ins * inm[j]);
            #pragma unroll
            for (int o = 8; o; o >>= 1) mx = fmaxf(mx, __shfl_xor_sync(0xFFFFFFFFu, mx, o));
            if (tx == 0) g_blockmax[blockIdx.x * B_ + row0 + i] = mx;
        }
    } else {
        float bj[4];
        #pragma unroll
        for (int j = 0; j < 4; j++) bj[j] = bias ? bias[col0 + j] : 0.f;
        float* Cb = C + (size_t)blockIdx.z * cB;
        #pragma unroll
        for (int i = 0; i < 8; i++) {
            float v[4];
            #pragma unroll
            for (int j = 0; j < 4; j++) {
                v[j] = acc[i][j] + bj[j];
                if (MODE == 2) v[j] = fmaxf(v[j], 0.f);
            }
            *(float4*)&Cb[(size_t)(row0 + i) * ldc + col0] = make_float4(v[0], v[1], v[2], v[3]);
        }
    }
}

// ---------------- softmax over [M logits + self], normalized in place --------
__global__ void softmax_kernel(float* __restrict__ logits, const float* __restrict__ projsrc,
                               float* __restrict__ pself) {
    int h = blockIdx.x >> 8, b = blockIdx.x & 255;
    int tid = threadIdx.x, w = tid >> 5, lane = tid & 31;
    float* row = logits + ((size_t)(h * B_ + b)) * M_;

    __shared__ float s_ls, smax[8], ssum[8];
    if (tid < 32) {
        float q = projsrc[b * 768 + h * 32 + tid];
        float k = projsrc[b * 768 + 256 + h * 32 + tid];
        float d = q * k;
        #pragma unroll
        for (int o = 16; o; o >>= 1) d += __shfl_xor_sync(0xFFFFFFFFu, d, o);
        if (tid == 0) s_ls = d * SCALE_;
    }
    float4 v0 = ((const float4*)row)[tid * 2];
    float4 v1 = ((const float4*)row)[tid * 2 + 1];
    float x[8] = {v0.x, v0.y, v0.z, v0.w, v1.x, v1.y, v1.z, v1.w};
    float lmax = -1e30f;
    #pragma unroll
    for (int j = 0; j < 8; j++) { x[j] *= SCALE_; lmax = fmaxf(lmax, x[j]); }
    #pragma unroll
    for (int o = 16; o; o >>= 1) lmax = fmaxf(lmax, __shfl_xor_sync(0xFFFFFFFFu, lmax, o));
    if (lane == 0) smax[w] = lmax;
    __syncthreads();
    float gmax = s_ls;
    #pragma unroll
    for (int i = 0; i < 8; i++) gmax = fmaxf(gmax, smax[i]);
    float lsum = 0.f;
    #pragma unroll
    for (int j = 0; j < 8; j++) { x[j] = __expf(x[j] - gmax); lsum += x[j]; }
    #pragma unroll
    for (int o = 16; o; o >>= 1) lsum += __shfl_xor_sync(0xFFFFFFFFu, lsum, o);
    if (lane == 0) ssum[w] = lsum;
    __syncthreads();
    float eself = __expf(s_ls - gmax);
    float tot = eself;
    #pragma unroll
    for (int i = 0; i < 8; i++) tot += ssum[i];
    float inv = 1.f / tot;
    #pragma unroll
    for (int j = 0; j < 8; j++) x[j] *= inv;
    ((float4*)row)[tid * 2]     = make_float4(x[0], x[1], x[2], x[3]);
    ((float4*)row)[tid * 2 + 1] = make_float4(x[4], x[5], x[6], x[7]);
    if (tid == 0) pself[h * B_ + b] = eself * inv;
}

// ---------------- AV split-K: tile 128 rows x 32 cols, 128 thr, 8x4 micro ----
__global__ void __launch_bounds__(128)
av_kernel(const float* __restrict__ probs, const float* __restrict__ kv,
          float* __restrict__ part) {
    __shared__ float Ps[2][16][128];
    __shared__ float Vs[2][16][32];
    int tid = threadIdx.x;
    int tx = tid & 7, ty = tid >> 3;
    int qb = blockIdx.x, split = blockIdx.y, h = blockIdx.z;

    const float* Prow = probs + ((size_t)(h * B_ + qb * 128 + tid)) * M_ + split * KSPLIT_;
    int vr = tid >> 3, vc = (tid & 7) * 4;
    const float* Vp = kv + (size_t)(split * KSPLIT_ + vr) * 512 + 256 + h * 32 + vc;

    float4 p0, p1, p2, p3, vv;
    p0 = *(const float4*)(Prow);     p1 = *(const float4*)(Prow + 4);
    p2 = *(const float4*)(Prow + 8); p3 = *(const float4*)(Prow + 12);
    vv = *(const float4*)(Vp);
    {
        Ps[0][0][tid]=p0.x; Ps[0][1][tid]=p0.y; Ps[0][2][tid]=p0.z; Ps[0][3][tid]=p0.w;
        Ps[0][4][tid]=p1.x; Ps[0][5][tid]=p1.y; Ps[0][6][tid]=p1.z; Ps[0][7][tid]=p1.w;
        Ps[0][8][tid]=p2.x; Ps[0][9][tid]=p2.y; Ps[0][10][tid]=p2.z; Ps[0][11][tid]=p2.w;
        Ps[0][12][tid]=p3.x; Ps[0][13][tid]=p3.y; Ps[0][14][tid]=p3.z; Ps[0][15][tid]=p3.w;
        *(float4*)&Vs[0][vr][vc] = vv;
    }
    __syncthreads();

    float acc[8][4] = {};
    const int nIt = KSPLIT_ / 16;
    for (int it = 0; it < nIt; ++it) {
        int buf = it & 1;
        bool more = (it + 1) < nIt;
        if (more) {
            int k0 = (it + 1) * 16;
            p0 = *(const float4*)(Prow + k0);      p1 = *(const float4*)(Prow + k0 + 4);
            p2 = *(const float4*)(Prow + k0 + 8);  p3 = *(const float4*)(Prow + k0 + 12);
            vv = *(const float4*)(Vp + (size_t)k0 * 512);
        }
        #pragma unroll
        for (int kk = 0; kk < 16; kk++) {
            float a[8], b[4];
            *(float4*)&a[0] = *(const float4*)&Ps[buf][kk][ty * 8];
            *(float4*)&a[4] = *(const float4*)&Ps[buf][kk][ty * 8 + 4];
            *(float4*)&b[0] = *(const float4*)&Vs[buf][kk][tx * 4];
            #pragma unroll
            for (int i = 0; i < 8; i++)
                #pragma unroll
                for (int j = 0; j < 4; j++) acc[i][j] += a[i] * b[j];
        }
        if (more) {
            int nb = buf ^ 1;
            Ps[nb][0][tid]=p0.x; Ps[nb][1][tid]=p0.y; Ps[nb][2][tid]=p0.z; Ps[nb][3][tid]=p0.w;
            Ps[nb][4][tid]=p1.x; Ps[nb][5][tid]=p1.y; Ps[nb][6][tid]=p1.z; Ps[nb][7][tid]=p1.w;
            Ps[nb][8][tid]=p2.x; Ps[nb][9][tid]=p2.y; Ps[nb][10][tid]=p2.z; Ps[nb][11][tid]=p2.w;
            Ps[nb][12][tid]=p3.x; Ps[nb][13][tid]=p3.y; Ps[nb][14][tid]=p3.z; Ps[nb][15][tid]=p3.w;
            *(float4*)&Vs[nb][vr][vc] = vv;
            __syncthreads();
        }
    }
    #pragma unroll
    for (int i = 0; i < 8; i++) {
        *(float4*)&part[(size_t)split * (B_ * D_) +
                        (size_t)(qb * 128 + ty * 8 + i) * D_ + h * 32 + tx * 4]
            = make_float4(acc[i][0], acc[i][1], acc[i][2], acc[i][3]);
    }
}

// ---------------- reduce AV partials + self term -> ctx ----------------------
__global__ void reduce_ctx_kernel(const float* __restrict__ part, const float* __restrict__ pself,
                                  const float* __restrict__ projsrc, float* __restrict__ ctx) {
    int b = blockIdx.x, d = threadIdx.x;
    int h = d >> 5;
    float s = 0.f;
    #pragma unroll
    for (int sp = 0; sp < NSPLIT_; sp++) s += part[(size_t)sp * (B_ * D_) + b * D_ + d];
    s += pself[h * B_ + b] * projsrc[b * 768 + 512 + d];
    ctx[b * D_ + d] = s;
}

// ---------------- LN with fused split-K reduce -------------------------------
__global__ void ln_split_kernel(const float* __restrict__ a, const float* __restrict__ part,
                                int nsplit, const float* __restrict__ bias,
                                const float* __restrict__ g, const float* __restrict__ be,
                                float* __restrict__ out) {
    int w = threadIdx.x >> 5, lane = threadIdx.x & 31;
    int row = blockIdx.x * 8 + w;
    size_t base = (size_t)row * D_ + lane * 8;
    float4 a0 = *(const float4*)(a + base);
    float4 a1 = *(const float4*)(a + base + 4);
    float x[8] = {a0.x, a0.y, a0.z, a0.w, a1.x, a1.y, a1.z, a1.w};
    for (int z = 0; z < nsplit; z++) {
        const float* pp = part + (size_t)z * (B_ * D_) + base;
        float4 p0 = *(const float4*)pp;
        float4 p1 = *(const float4*)(pp + 4);
        x[0]+=p0.x; x[1]+=p0.y; x[2]+=p0.z; x[3]+=p0.w;
        x[4]+=p1.x; x[5]+=p1.y; x[6]+=p1.z; x[7]+=p1.w;
    }
    float4 bb0 = *(const float4*)(bias + lane * 8);
    float4 bb1 = *(const float4*)(bias + lane * 8 + 4);
    x[0]+=bb0.x; x[1]+=bb0.y; x[2]+=bb0.z; x[3]+=bb0.w;
    x[4]+=bb1.x; x[5]+=bb1.y; x[6]+=bb1.z; x[7]+=bb1.w;

    float s = 0.f;
    #pragma unroll
    for (int j = 0; j < 8; j++) s += x[j];
    #pragma unroll
    for (int o = 16; o; o >>= 1) s += __shfl_xor_sync(0xFFFFFFFFu, s, o);
    float mean = s * (1.f / D_);
    float v = 0.f;
    #pragma unroll
    for (int j = 0; j < 8; j++) { float c = x[j] - mean; v += c * c; }
    #pragma unroll
    for (int o = 16; o; o >>= 1) v += __shfl_xor_sync(0xFFFFFFFFu, v, o);
    float rstd = rsqrtf(v * (1.f / D_) + 1e-5f);
    float4 g0 = *(const float4*)(g + lane * 8);
    float4 g1 = *(const float4*)(g + lane * 8 + 4);
    float4 e0 = *(const float4*)(be + lane * 8);
    float4 e1 = *(const float4*)(be + lane * 8 + 4);
    float gg[8] = {g0.x, g0.y, g0.z, g0.w, g1.x, g1.y, g1.z, g1.w};
    float ee[8] = {e0.x, e0.y, e0.z, e0.w, e1.x, e1.y, e1.z, e1.w};
    float o8[8];
    #pragma unroll
    for (int j = 0; j < 8; j++) o8[j] = (x[j] - mean) * rstd * gg[j] + ee[j];
    *(float4*)(out + base)     = make_float4(o8[0], o8[1], o8[2], o8[3]);
    *(float4*)(out + base + 4) = make_float4(o8[4], o8[5], o8[6], o8[7]);
}

// ---------------- scatter prep: ballot-scan prefix ----------------------------
__global__ void scatter_prep_kernel(const int* __restrict__ ptrp) {
    __shared__ float red[256];
    __shared__ int wcnt[8];
    int t = threadIdx.x, w = t >> 5, lane = t & 31;
    float f = 0.f;
    #pragma unroll
    for (int j = 0; j < 8; j++) f += g_mem_sq[t + j * 256];
    red[t] = f; __syncthreads();
    #pragma unroll
    for (int o = 128; o; o >>= 1) { if (t < o) red[t] += red[t + o]; __syncthreads(); }
    int flag = red[0] > 0.f;
    float mx = -1e30f;
    #pragma unroll
    for (int bn = 0; bn < 32; bn++) mx = fmaxf(mx, g_blockmax[bn * B_ + t]);
    float s = flag ? (1.0f - mx) : 1.0f;
    int ptr = *ptrp;
    long long forced = (long long)M_ - (long long)ptr;
    int cond = (s > THR_) || ((long long)t < forced);
    // warp-level exclusive prefix of cond via ballot
    unsigned mask = __ballot_sync(0xFFFFFFFFu, cond);
    int lpref = __popc(mask & ((1u << lane) - 1u));
    if (lane == 31) wcnt[w] = lpref + cond;
    #pragma unroll
    for (int j = 0; j < 8; j++) g_row_src[t + j * 256] = -1;
    __syncthreads();
    int wbase = 0;
    #pragma unroll
    for (int i = 0; i < 8; i++) { if (i < w) wbase += wcnt[i]; }
    g_upd_s[t] = s;
    if (cond) {
        long long p = (long long)ptr + (wbase + lpref);
        int idx = (int)(p % M_); if (idx < 0) idx += M_;
        g_row_src[idx] = t;
    }
}

// ---------------- full-coverage memory update --------------------------------
__global__ void update_kernel(const float* __restrict__ mem, const float* __restrict__ mom,
                              const float* __restrict__ scores,
                              float* __restrict__ out_mem, float* __restrict__ out_mom,
                              float* __restrict__ out_sc) {
    int row = blockIdx.x, t = threadIdx.x;
    int i = g_row_src[row];
    size_t o = (size_t)row * D_ + t;
    float mval = mem[o], mo = mom[o];
    if (i >= 0) {
        float diff = g_h[i * D_ + t] - mval;
        float nm = MOM_ * mo + (1.0f - MOM_) * diff;
        out_mem[o] = mval + LR_ * nm;
        out_mom[o] = nm;
    } else {
        out_mem[o] = mval;
        out_mom[o] = mo;
    }
    if (t == 0) out_sc[row] = (i >= 0) ? g_upd_s[i] : scores[row];
}

// ---------------- launch -----------------------------------------------------
extern "C" void kernel_launch(void* const* d_in, const int* in_sizes, int n_in,
                              void* d_out, int out_size) {
    const float* src       = (const float*)d_in[0];
    const float* memory    = (const float*)d_in[1];
    const float* momentum  = (const float*)d_in[2];
    const float* scores    = (const float*)d_in[3];
    const float* in_proj_w = (const float*)d_in[4];
    const float* in_proj_b = (const float*)d_in[5];
    const float* out_w     = (const float*)d_in[6];
    const float* out_b     = (const float*)d_in[7];
    const float* w1        = (const float*)d_in[8];
    const float* b1        = (const float*)d_in[9];
    const float* w2        = (const float*)d_in[10];
    const float* b2        = (const float*)d_in[11];
    const float* g1        = (const float*)d_in[12];
    const float* be1       = (const float*)d_in[13];
    const float* g2        = (const float*)d_in[14];
    const float* be2       = (const float*)d_in[15];
    const int*   ptr       = (const int*)d_in[16];

    float* out     = (float*)d_out;
    float* out_mem = out + B_ * D_;
    float* out_mom = out_mem + M_ * D_;
    float* out_sc  = out_mom + M_ * D_;

    float *proj_p, *kv_p, *log_p, *pself_p, *part_p, *ap_p, *fp_p, *ctx_p, *h_p, *hid_p;
    cudaGetSymbolAddress((void**)&proj_p,  g_proj_src);
    cudaGetSymbolAddress((void**)&kv_p,    g_kv_mem);
    cudaGetSymbolAddress((void**)&log_p,   g_logits);
    cudaGetSymbolAddress((void**)&pself_p, g_pself);
    cudaGetSymbolAddress((void**)&part_p,  g_ctx_part);
    cudaGetSymbolAddress((void**)&ap_p,    g_attn_part);
    cudaGetSymbolAddress((void**)&fp_p,    g_ff_part);
    cudaGetSymbolAddress((void**)&ctx_p,   g_ctx);
    cudaGetSymbolAddress((void**)&h_p,     g_h);
    cudaGetSymbolAddress((void**)&hid_p,   g_hidden);

    static cudaStream_t s1 = nullptr, s2 = nullptr;
    static cudaEvent_t eFork = nullptr, eK = nullptr, eKV = nullptr, eS2 = nullptr,
                       eLN1 = nullptr, eUpd = nullptr;
    if (!s1) {
        cudaStreamCreateWithFlags(&s1, cudaStreamNonBlocking);
        cudaStreamCreateWithFlags(&s2, cudaStreamNonBlocking);
        cudaEventCreateWithFlags(&eFork, cudaEventDisableTiming);
        cudaEventCreateWithFlags(&eK,    cudaEventDisableTiming);
        cudaEventCreateWithFlags(&eKV,   cudaEventDisableTiming);
        cudaEventCreateWithFlags(&eS2,   cudaEventDisableTiming);
        cudaEventCreateWithFlags(&eLN1,  cudaEventDisableTiming);
        cudaEventCreateWithFlags(&eUpd,  cudaEventDisableTiming);
    }

    // ---- fork ----
    cudaEventRecord(eFork, 0);
    cudaStreamWaitEvent(s1, eFork, 0);
    cudaStreamWaitEvent(s2, eFork, 0);

    // S1: memory K projection (gates logits), then V projection
    sgemm128<0><<<dim3(4, 32, 1), 128, 0, s1>>>(memory, in_proj_w + D_ * D_, in_proj_b + D_, kv_p,
                                                256, 256, 256, 512, 0, 0, 0);
    cudaEventRecord(eK, s1);
    sgemm128<0><<<dim3(4, 32, 1), 128, 0, s1>>>(memory, in_proj_w + 2 * D_ * D_, in_proj_b + 2 * D_,
                                                kv_p + 256, 256, 256, 256, 512, 0, 0, 0);
    cudaEventRecord(eKV, s1);

    // S2: norms -> cosine blockmax -> scatter prep
    norms_kernel<<<(B_ + M_ + 7) / 8, dim3(32, 8), 0, s2>>>(src, memory);
    sgemm128<1><<<dim3(32, 4, 1), 128, 0, s2>>>(src, memory, nullptr, nullptr,
                                                256, 256, 256, 0, 0, 0, 0);
    scatter_prep_kernel<<<1, 256, 0, s2>>>(ptr);
    cudaEventRecord(eS2, s2);

    // S0: src projections [256,768]
    sgemm128<0><<<dim3(12, 4, 1), 128>>>(src, in_proj_w, in_proj_b, proj_p,
                                         256, 256, 256, 768, 0, 0, 0);

    // S0: attention chain (logits needs only K half)
    cudaStreamWaitEvent(0, eK, 0);
    sgemm128<0><<<dim3(32, 4, H_), 128>>>(proj_p, kv_p, nullptr, log_p,
                                          32, 768, 512, 2048, 32, 32, B_ * M_);
    softmax_kernel<<<H_ * B_, 256>>>(log_p, proj_p, pself_p);
    cudaStreamWaitEvent(0, eKV, 0);
    av_kernel<<<dim3(2, NSPLIT_, H_), 128>>>(log_p, kv_p, part_p);
    reduce_ctx_kernel<<<B_, 256>>>(part_p, pself_p, proj_p, ctx_p);

    // out-proj split-K x4 -> partials; LN1 fuses reduce + bias
    sgemm128<0><<<dim3(4, 4, 4), 128>>>(ctx_p, out_w, nullptr, ap_p,
                                        64, 256, 256, 256, 64, 64, B_ * D_);
    ln_split_kernel<<<B_ / 8, 256>>>(src, ap_p, 4, out_b, g1, be1, h_p);
    cudaEventRecord(eLN1, 0);

    // S1: memory update path (needs h + scatter map), overlaps FFN
    cudaStreamWaitEvent(s1, eLN1, 0);
    cudaStreamWaitEvent(s1, eS2, 0);
    update_kernel<<<M_, 256, 0, s1>>>(memory, momentum, scores, out_mem, out_mom, out_sc);
    cudaEventRecord(eUpd, s1);

    // S0: FFN1 (relu+bias), FFN2 split-K x16 -> partials; LN2 fuses reduce
    sgemm128<2><<<dim3(16, 4, 1), 128>>>(h_p, w1, b1, hid_p,
                                         256, 256, 256, 1024, 0, 0, 0);
    sgemm128<0><<<dim3(4, 4, FSPLIT_), 128>>>(hid_p, w2, nullptr, fp_p,
                                              1024 / FSPLIT_, 1024, 1024, 256,
                                              1024 / FSPLIT_, 1024 / FSPLIT_, B_ * D_);
    ln_split_kernel<<<B_ / 8, 256>>>(h_p, fp_p, FSPLIT_, b2, g2, be2, out);

    // ---- join ----
    cudaStreamWaitEvent(0, eUpd, 0);
}

// round 6
// speedup vs baseline: 1.1926x; 1.1926x over previous
#include <cuda_runtime.h>
#include <math.h>
#include <stdint.h>

#define B_   256
#define D_   256
#define H_   8
#define HD_  32
#define FF_  1024
#define M_   2048
#define SCALE_ 0.17677669529663687f   /* 1/sqrt(32) */
#define THR_ 0.5f
#define MOM_ 0.9f
#define LR_  0.1f
#define NSPLIT_ 16
#define KSPLIT_ (M_ / NSPLIT_)   /* 128 keys per split */
#define FSPLIT_ 16               /* FFN2 split-K */

// ---------------- scratch (device globals) -----------------------------------
__device__ float g_proj_src[B_ * 3 * D_];
__device__ float g_kv_mem[M_ * 2 * D_];
__device__ float g_logits[H_ * B_ * M_];
__device__ float g_pself[H_ * B_];
__device__ float g_ctx_part[NSPLIT_ * B_ * D_];
__device__ float g_attn_part[4 * B_ * D_];
__device__ float g_ff_part[FSPLIT_ * B_ * D_];
__device__ float g_blockmax[32 * B_];
__device__ float g_src_norm[B_];
__device__ float g_mem_norm[M_];
__device__ float g_mem_sq[M_];
__device__ float g_ctx[B_ * D_];
__device__ float g_h[B_ * D_];
__device__ float g_hidden[B_ * FF_];
__device__ int   g_row_src[M_];
__device__ float g_upd_s[B_];

__device__ __forceinline__ uint32_t f2tf32(float f) {
    uint32_t r;
    asm("cvt.rna.tf32.f32 %0, %1;" : "=r"(r) : "f"(f));
    return r;
}

__device__ __forceinline__ void mma_tf32(float c[4], const uint32_t a[4], const uint32_t b[2]) {
    asm volatile(
        "mma.sync.aligned.m16n8k8.row.col.f32.tf32.tf32.f32 "
        "{%0,%1,%2,%3}, {%4,%5,%6,%7}, {%8,%9}, {%0,%1,%2,%3};"
        : "+f"(c[0]), "+f"(c[1]), "+f"(c[2]), "+f"(c[3])
        : "r"(a[0]), "r"(a[1]), "r"(a[2]), "r"(a[3]), "r"(b[0]), "r"(b[1]));
}

// ---------------- row norms --------------------------------------------------
__global__ void norms_kernel(const float* __restrict__ src, const float* __restrict__ mem) {
    int row = blockIdx.x * 8 + threadIdx.y;
    int lane = threadIdx.x;
    if (row >= B_ + M_) return;
    bool is_src = row < B_;
    const float* base = is_src ? (src + row * D_) : (mem + (row - B_) * D_);
    float s = 0.f;
    #pragma unroll
    for (int d = lane; d < D_; d += 32) { float v = base[d]; s += v * v; }
    #pragma unroll
    for (int o = 16; o; o >>= 1) s += __shfl_xor_sync(0xFFFFFFFFu, s, o);
    if (lane == 0) {
        float nv = fmaxf(sqrtf(s), 1e-8f);
        if (is_src) g_src_norm[row] = nv;
        else { g_mem_norm[row - B_] = nv; g_mem_sq[row - B_] = s; }
    }
}

// ---------------- TF32 tensor-core GEMM: C[.,N]=A@B^T, 64x64 tile, 128 thr ---
// MODE 0: (+bias) store. MODE 2: relu(+bias) store.
template <int MODE>
__global__ void __launch_bounds__(128)
tmma64(const float* __restrict__ A, const float* __restrict__ Bm,
       const float* __restrict__ bias, float* __restrict__ C,
       int K, int lda, int ldb, int ldc, int aB, int bB, int cB) {
    __shared__ uint32_t As[2][16][72];   // [k][row], stride 72 -> conflict-free frags
    __shared__ uint32_t Bs[2][16][72];   // [k][col]
    int tid = threadIdx.x;
    int r = tid & 63, half = tid >> 6;
    int h8 = half * 8;
    const float* Ap = A + (size_t)blockIdx.z * aB + (size_t)(blockIdx.y * 64 + r) * lda + h8;
    const float* Bp = Bm + (size_t)blockIdx.z * bB + (size_t)(blockIdx.x * 64 + r) * ldb + h8;

    float4 a0 = *(const float4*)(Ap);
    float4 a1 = *(const float4*)(Ap + 4);
    float4 b0 = *(const float4*)(Bp);
    float4 b1 = *(const float4*)(Bp + 4);
    As[0][h8 + 0][r] = f2tf32(a0.x); As[0][h8 + 1][r] = f2tf32(a0.y);
    As[0][h8 + 2][r] = f2tf32(a0.z); As[0][h8 + 3][r] = f2tf32(a0.w);
    As[0][h8 + 4][r] = f2tf32(a1.x); As[0][h8 + 5][r] = f2tf32(a1.y);
    As[0][h8 + 6][r] = f2tf32(a1.z); As[0][h8 + 7][r] = f2tf32(a1.w);
    Bs[0][h8 + 0][r] = f2tf32(b0.x); Bs[0][h8 + 1][r] = f2tf32(b0.y);
    Bs[0][h8 + 2][r] = f2tf32(b0.z); Bs[0][h8 + 3][r] = f2tf32(b0.w);
    Bs[0][h8 + 4][r] = f2tf32(b1.x); Bs[0][h8 + 5][r] = f2tf32(b1.y);
    Bs[0][h8 + 6][r] = f2tf32(b1.z); Bs[0][h8 + 7][r] = f2tf32(b1.w);
    __syncthreads();

    int warp = tid >> 5, lane = tid & 31;
    int wm = warp & 1, wn = warp >> 1;      // warp 32x32 sub-tile
    int lr = lane >> 2, lc = lane & 3;

    float acc[2][4][4];
    #pragma unroll
    for (int mt = 0; mt < 2; mt++)
        #pragma unroll
        for (int nt = 0; nt < 4; nt++)
            #pragma unroll
            for (int q = 0; q < 4; q++) acc[mt][nt][q] = 0.f;

    int nIt = K >> 4;
    for (int it = 0; it < nIt; ++it) {
        int buf = it & 1;
        bool more = (it + 1) < nIt;
        if (more) {
            int k0 = (it + 1) << 4;
            a0 = *(const float4*)(Ap + k0);
            a1 = *(const float4*)(Ap + k0 + 4);
            b0 = *(const float4*)(Bp + k0);
            b1 = *(const float4*)(Bp + k0 + 4);
        }
        #pragma unroll
        for (int k8 = 0; k8 < 16; k8 += 8) {
            uint32_t af[2][4], bf[4][2];
            #pragma unroll
            for (int mt = 0; mt < 2; mt++) {
                int row = wm * 32 + mt * 16 + lr;
                af[mt][0] = As[buf][k8 + lc][row];
                af[mt][1] = As[buf][k8 + lc][row + 8];
                af[mt][2] = As[buf][k8 + lc + 4][row];
                af[mt][3] = As[buf][k8 + lc + 4][row + 8];
            }
            #pragma unroll
            for (int nt = 0; nt < 4; nt++) {
                int col = wn * 32 + nt * 8 + lr;
                bf[nt][0] = Bs[buf][k8 + lc][col];
                bf[nt][1] = Bs[buf][k8 + lc + 4][col];
            }
            #pragma unroll
            for (int mt = 0; mt < 2; mt++)
                #pragma unroll
                for (int nt = 0; nt < 4; nt++) mma_tf32(acc[mt][nt], af[mt], bf[nt]);
        }
        if (more) {
            int nb = buf ^ 1;
            As[nb][h8 + 0][r] = f2tf32(a0.x); As[nb][h8 + 1][r] = f2tf32(a0.y);
            As[nb][h8 + 2][r] = f2tf32(a0.z); As[nb][h8 + 3][r] = f2tf32(a0.w);
            As[nb][h8 + 4][r] = f2tf32(a1.x); As[nb][h8 + 5][r] = f2tf32(a1.y);
            As[nb][h8 + 6][r] = f2tf32(a1.z); As[nb][h8 + 7][r] = f2tf32(a1.w);
            Bs[nb][h8 + 0][r] = f2tf32(b0.x); Bs[nb][h8 + 1][r] = f2tf32(b0.y);
            Bs[nb][h8 + 2][r] = f2tf32(b0.z); Bs[nb][h8 + 3][r] = f2tf32(b0.w);
            Bs[nb][h8 + 4][r] = f2tf32(b1.x); Bs[nb][h8 + 5][r] = f2tf32(b1.y);
            Bs[nb][h8 + 6][r] = f2tf32(b1.z); Bs[nb][h8 + 7][r] = f2tf32(b1.w);
            __syncthreads();
        }
    }

    float* Cb = C + (size_t)blockIdx.z * cB;
    #pragma unroll
    for (int mt = 0; mt < 2; mt++) {
        #pragma unroll
        for (int nt = 0; nt < 4; nt++) {
            int col_g = blockIdx.x * 64 + wn * 32 + nt * 8 + 2 * lc;
            float bj0 = bias ? bias[col_g] : 0.f;
            float bj1 = bias ? bias[col_g + 1] : 0.f;
            #pragma unroll
            for (int hrow = 0; hrow < 2; hrow++) {
                int row_g = blockIdx.y * 64 + wm * 32 + mt * 16 + lr + hrow * 8;
                float v0 = acc[mt][nt][hrow * 2 + 0] + bj0;
                float v1 = acc[mt][nt][hrow * 2 + 1] + bj1;
                if (MODE == 2) { v0 = fmaxf(v0, 0.f); v1 = fmaxf(v1, 0.f); }
                *(float2*)&Cb[(size_t)row_g * ldc + col_g] = make_float2(v0, v1);
            }
        }
    }
}

// ---------------- fp32 SGEMM (cosine branch only): 64x64, 128 thr, 8x4 micro -
__global__ void __launch_bounds__(128)
sgemm_cos(const float* __restrict__ A, const float* __restrict__ Bm, int K, int lda, int ldb) {
    __shared__ float As[2][16][64];
    __shared__ float Bs[2][16][64];
    int tid = threadIdx.x;
    int tx = tid & 15, ty = tid >> 4;
    int r = tid & 63, half = tid >> 6;
    int h8 = half * 8;
    const float* Ap = A + (size_t)(blockIdx.y * 64 + r) * lda + h8;
    const float* Bp = Bm + (size_t)(blockIdx.x * 64 + r) * ldb + h8;

    float4 a0 = *(const float4*)(Ap);
    float4 a1 = *(const float4*)(Ap + 4);
    float4 b0 = *(const float4*)(Bp);
    float4 b1 = *(const float4*)(Bp + 4);
    As[0][h8 + 0][r] = a0.x; As[0][h8 + 1][r] = a0.y; As[0][h8 + 2][r] = a0.z; As[0][h8 + 3][r] = a0.w;
    As[0][h8 + 4][r] = a1.x; As[0][h8 + 5][r] = a1.y; As[0][h8 + 6][r] = a1.z; As[0][h8 + 7][r] = a1.w;
    Bs[0][h8 + 0][r] = b0.x; Bs[0][h8 + 1][r] = b0.y; Bs[0][h8 + 2][r] = b0.z; Bs[0][h8 + 3][r] = b0.w;
    Bs[0][h8 + 4][r] = b1.x; Bs[0][h8 + 5][r] = b1.y; Bs[0][h8 + 6][r] = b1.z; Bs[0][h8 + 7][r] = b1.w;
    __syncthreads();

    float acc[8][4] = {};
    int nIt = K >> 4;
    for (int it = 0; it < nIt; ++it) {
        int buf = it & 1;
        bool more = (it + 1) < nIt;
        if (more) {
            int k0 = (it + 1) << 4;
            a0 = *(const float4*)(Ap + k0);
            a1 = *(const float4*)(Ap + k0 + 4);
            b0 = *(const float4*)(Bp + k0);
            b1 = *(const float4*)(Bp + k0 + 4);
        }
        #pragma unroll
        for (int kk = 0; kk < 16; kk++) {
            float a[8], b[4];
            *(float4*)&a[0] = *(const float4*)&As[buf][kk][ty * 8];
            *(float4*)&a[4] = *(const float4*)&As[buf][kk][ty * 8 + 4];
            *(float4*)&b[0] = *(const float4*)&Bs[buf][kk][tx * 4];
            #pragma unroll
            for (int i = 0; i < 8; i++)
                #pragma unroll
                for (int j = 0; j < 4; j++) acc[i][j] += a[i] * b[j];
        }
        if (more) {
            int nb = buf ^ 1;
            As[nb][h8 + 0][r] = a0.x; As[nb][h8 + 1][r] = a0.y; As[nb][h8 + 2][r] = a0.z; As[nb][h8 + 3][r] = a0.w;
            As[nb][h8 + 4][r] = a1.x; As[nb][h8 + 5][r] = a1.y; As[nb][h8 + 6][r] = a1.z; As[nb][h8 + 7][r] = a1.w;
            Bs[nb][h8 + 0][r] = b0.x; Bs[nb][h8 + 1][r] = b0.y; Bs[nb][h8 + 2][r] = b0.z; Bs[nb][h8 + 3][r] = b0.w;
            Bs[nb][h8 + 4][r] = b1.x; Bs[nb][h8 + 5][r] = b1.y; Bs[nb][h8 + 6][r] = b1.z; Bs[nb][h8 + 7][r] = b1.w;
            __syncthreads();
        }
    }

    int row0 = blockIdx.y * 64 + ty * 8;
    int col0 = blockIdx.x * 64 + tx * 4;
    float inm[4];
    #pragma unroll
    for (int j = 0; j < 4; j++) inm[j] = 1.f / g_mem_norm[col0 + j];
    #pragma unroll
    for (int i = 0; i < 8; i++) {
        float ins = 1.f / g_src_norm[row0 + i];
        float mx = -1e30f;
        #pragma unroll
        for (int j = 0; j < 4; j++) mx = fmaxf(mx, acc[i][j] * ins * inm[j]);
        #pragma unroll
        for (int o = 8; o; o >>= 1) mx = fmaxf(mx, __shfl_xor_sync(0xFFFFFFFFu, mx, o));
        if (tx == 0) g_blockmax[blockIdx.x * B_ + row0 + i] = mx;
    }
}

// ---------------- softmax over [M logits + self], normalized in place --------
__global__ void softmax_kernel(float* __restrict__ logits, const float* __restrict__ projsrc,
                               float* __restrict__ pself) {
    int h = blockIdx.x >> 8, b = blockIdx.x & 255;
    int tid = threadIdx.x, w = tid >> 5, lane = tid & 31;
    float* row = logits + ((size_t)(h * B_ + b)) * M_;

    __shared__ float s_ls, smax[8], ssum[8];
    if (tid < 32) {
        float q = projsrc[b * 768 + h * 32 + tid];
        float k = projsrc[b * 768 + 256 + h * 32 + tid];
        float d = q * k;
        #pragma unroll
        for (int o = 16; o; o >>= 1) d += __shfl_xor_sync(0xFFFFFFFFu, d, o);
        if (tid == 0) s_ls = d * SCALE_;
    }
    float4 v0 = ((const float4*)row)[tid * 2];
    float4 v1 = ((const float4*)row)[tid * 2 + 1];
    float x[8] = {v0.x, v0.y, v0.z, v0.w, v1.x, v1.y, v1.z, v1.w};
    float lmax = -1e30f;
    #pragma unroll
    for (int j = 0; j < 8; j++) { x[j] *= SCALE_; lmax = fmaxf(lmax, x[j]); }
    #pragma unroll
    for (int o = 16; o; o >>= 1) lmax = fmaxf(lmax, __shfl_xor_sync(0xFFFFFFFFu, lmax, o));
    if (lane == 0) smax[w] = lmax;
    __syncthreads();
    float gmax = s_ls;
    #pragma unroll
    for (int i = 0; i < 8; i++) gmax = fmaxf(gmax, smax[i]);
    float lsum = 0.f;
    #pragma unroll
    for (int j = 0; j < 8; j++) { x[j] = __expf(x[j] - gmax); lsum += x[j]; }
    #pragma unroll
    for (int o = 16; o; o >>= 1) lsum += __shfl_xor_sync(0xFFFFFFFFu, lsum, o);
    if (lane == 0) ssum[w] = lsum;
    __syncthreads();
    float eself = __expf(s_ls - gmax);
    float tot = eself;
    #pragma unroll
    for (int i = 0; i < 8; i++) tot += ssum[i];
    float inv = 1.f / tot;
    #pragma unroll
    for (int j = 0; j < 8; j++) x[j] *= inv;
    ((float4*)row)[tid * 2]     = make_float4(x[0], x[1], x[2], x[3]);
    ((float4*)row)[tid * 2 + 1] = make_float4(x[4], x[5], x[6], x[7]);
    if (tid == 0) pself[h * B_ + b] = eself * inv;
}

// ---------------- AV split-K (fp32): tile 128x32, 128 thr, 8x4 micro ---------
__global__ void __launch_bounds__(128)
av_kernel(const float* __restrict__ probs, const float* __restrict__ kv,
          float* __restrict__ part) {
    __shared__ float Ps[2][16][128];
    __shared__ float Vs[2][16][32];
    int tid = threadIdx.x;
    int tx = tid & 7, ty = tid >> 3;
    int qb = blockIdx.x, split = blockIdx.y, h = blockIdx.z;

    const float* Prow = probs + ((size_t)(h * B_ + qb * 128 + tid)) * M_ + split * KSPLIT_;
    int vr = tid >> 3, vc = (tid & 7) * 4;
    const float* Vp = kv + (size_t)(split * KSPLIT_ + vr) * 512 + 256 + h * 32 + vc;

    float4 p0, p1, p2, p3, vv;
    p0 = *(const float4*)(Prow);     p1 = *(const float4*)(Prow + 4);
    p2 = *(const float4*)(Prow + 8); p3 = *(const float4*)(Prow + 12);
    vv = *(const float4*)(Vp);
    {
        Ps[0][0][tid]=p0.x; Ps[0][1][tid]=p0.y; Ps[0][2][tid]=p0.z; Ps[0][3][tid]=p0.w;
        Ps[0][4][tid]=p1.x; Ps[0][5][tid]=p1.y; Ps[0][6][tid]=p1.z; Ps[0][7][tid]=p1.w;
        Ps[0][8][tid]=p2.x; Ps[0][9][tid]=p2.y; Ps[0][10][tid]=p2.z; Ps[0][11][tid]=p2.w;
        Ps[0][12][tid]=p3.x; Ps[0][13][tid]=p3.y; Ps[0][14][tid]=p3.z; Ps[0][15][tid]=p3.w;
        *(float4*)&Vs[0][vr][vc] = vv;
    }
    __syncthreads();

    float acc[8][4] = {};
    const int nIt = KSPLIT_ / 16;
    for (int it = 0; it < nIt; ++it) {
        int buf = it & 1;
        bool more = (it + 1) < nIt;
        if (more) {
            int k0 = (it + 1) * 16;
            p0 = *(const float4*)(Prow + k0);      p1 = *(const float4*)(Prow + k0 + 4);
            p2 = *(const float4*)(Prow + k0 + 8);  p3 = *(const float4*)(Prow + k0 + 12);
            vv = *(const float4*)(Vp + (size_t)k0 * 512);
        }
        #pragma unroll
        for (int kk = 0; kk < 16; kk++) {
            float a[8], b[4];
            *(float4*)&a[0] = *(const float4*)&Ps[buf][kk][ty * 8];
            *(float4*)&a[4] = *(const float4*)&Ps[buf][kk][ty * 8 + 4];
            *(float4*)&b[0] = *(const float4*)&Vs[buf][kk][tx * 4];
            #pragma unroll
            for (int i = 0; i < 8; i++)
                #pragma unroll
                for (int j = 0; j < 4; j++) acc[i][j] += a[i] * b[j];
        }
        if (more) {
            int nb = buf ^ 1;
            Ps[nb][0][tid]=p0.x; Ps[nb][1][tid]=p0.y; Ps[nb][2][tid]=p0.z; Ps[nb][3][tid]=p0.w;
            Ps[nb][4][tid]=p1.x; Ps[nb][5][tid]=p1.y; Ps[nb][6][tid]=p1.z; Ps[nb][7][tid]=p1.w;
            Ps[nb][8][tid]=p2.x; Ps[nb][9][tid]=p2.y; Ps[nb][10][tid]=p2.z; Ps[nb][11][tid]=p2.w;
            Ps[nb][12][tid]=p3.x; Ps[nb][13][tid]=p3.y; Ps[nb][14][tid]=p3.z; Ps[nb][15][tid]=p3.w;
            *(float4*)&Vs[nb][vr][vc] = vv;
            __syncthreads();
        }
    }
    #pragma unroll
    for (int i = 0; i < 8; i++) {
        *(float4*)&part[(size_t)split * (B_ * D_) +
                        (size_t)(qb * 128 + ty * 8 + i) * D_ + h * 32 + tx * 4]
            = make_float4(acc[i][0], acc[i][1], acc[i][2], acc[i][3]);
    }
}

// ---------------- reduce AV partials + self term -> ctx ----------------------
__global__ void reduce_ctx_kernel(const float* __restrict__ part, const float* __restrict__ pself,
                                  const float* __restrict__ projsrc, float* __restrict__ ctx) {
    int b = blockIdx.x, d = threadIdx.x;
    int h = d >> 5;
    float s = 0.f;
    #pragma unroll
    for (int sp = 0; sp < NSPLIT_; sp++) s += part[(size_t)sp * (B_ * D_) + b * D_ + d];
    s += pself[h * B_ + b] * projsrc[b * 768 + 512 + d];
    ctx[b * D_ + d] = s;
}

// ---------------- LN with fused split-K reduce -------------------------------
__global__ void ln_split_kernel(const float* __restrict__ a, const float* __restrict__ part,
                                int nsplit, const float* __restrict__ bias,
                                const float* __restrict__ g, const float* __restrict__ be,
                                float* __restrict__ out) {
    int w = threadIdx.x >> 5, lane = threadIdx.x & 31;
    int row = blockIdx.x * 8 + w;
    size_t base = (size_t)row * D_ + lane * 8;
    float4 a0 = *(const float4*)(a + base);
    float4 a1 = *(const float4*)(a + base + 4);
    float x[8] = {a0.x, a0.y, a0.z, a0.w, a1.x, a1.y, a1.z, a1.w};
    for (int z = 0; z < nsplit; z++) {
        const float* pp = part + (size_t)z * (B_ * D_) + base;
        float4 p0 = *(const float4*)pp;
        float4 p1 = *(const float4*)(pp + 4);
        x[0]+=p0.x; x[1]+=p0.y; x[2]+=p0.z; x[3]+=p0.w;
        x[4]+=p1.x; x[5]+=p1.y; x[6]+=p1.z; x[7]+=p1.w;
    }
    float4 bb0 = *(const float4*)(bias + lane * 8);
    float4 bb1 = *(const float4*)(bias + lane * 8 + 4);
    x[0]+=bb0.x; x[1]+=bb0.y; x[2]+=bb0.z; x[3]+=bb0.w;
    x[4]+=bb1.x; x[5]+=bb1.y; x[6]+=bb1.z; x[7]+=bb1.w;

    float s = 0.f;
    #pragma unroll
    for (int j = 0; j < 8; j++) s += x[j];
    #pragma unroll
    for (int o = 16; o; o >>= 1) s += __shfl_xor_sync(0xFFFFFFFFu, s, o);
    float mean = s * (1.f / D_);
    float v = 0.f;
    #pragma unroll
    for (int j = 0; j < 8; j++) { float c = x[j] - mean; v += c * c; }
    #pragma unroll
    for (int o = 16; o; o >>= 1) v += __shfl_xor_sync(0xFFFFFFFFu, v, o);
    float rstd = rsqrtf(v * (1.f / D_) + 1e-5f);
    float4 g0 = *(const float4*)(g + lane * 8);
    float4 g1 = *(const float4*)(g + lane * 8 + 4);
    float4 e0 = *(const float4*)(be + lane * 8);
    float4 e1 = *(const float4*)(be + lane * 8 + 4);
    float gg[8] = {g0.x, g0.y, g0.z, g0.w, g1.x, g1.y, g1.z, g1.w};
    float ee[8] = {e0.x, e0.y, e0.z, e0.w, e1.x, e1.y, e1.z, e1.w};
    float o8[8];
    #pragma unroll
    for (int j = 0; j < 8; j++) o8[j] = (x[j] - mean) * rstd * gg[j] + ee[j];
    *(float4*)(out + base)     = make_float4(o8[0], o8[1], o8[2], o8[3]);
    *(float4*)(out + base + 4) = make_float4(o8[4], o8[5], o8[6], o8[7]);
}

// ---------------- scatter prep: ballot-scan prefix ----------------------------
__global__ void scatter_prep_kernel(const int* __restrict__ ptrp) {
    __shared__ float red[256];
    __shared__ int wcnt[8];
    int t = threadIdx.x, w = t >> 5, lane = t & 31;
    float f = 0.f;
    #pragma unroll
    for (int j = 0; j < 8; j++) f += g_mem_sq[t + j * 256];
    red[t] = f; __syncthreads();
    #pragma unroll
    for (int o = 128; o; o >>= 1) { if (t < o) red[t] += red[t + o]; __syncthreads(); }
    int flag = red[0] > 0.f;
    float mx = -1e30f;
    #pragma unroll
    for (int bn = 0; bn < 32; bn++) mx = fmaxf(mx, g_blockmax[bn * B_ + t]);
    float s = flag ? (1.0f - mx) : 1.0f;
    int ptr = *ptrp;
    long long forced = (long long)M_ - (long long)ptr;
    int cond = (s > THR_) || ((long long)t < forced);
    unsigned mask = __ballot_sync(0xFFFFFFFFu, cond);
    int lpref = __popc(mask & ((1u << lane) - 1u));
    if (lane == 31) wcnt[w] = lpref + cond;
    #pragma unroll
    for (int j = 0; j < 8; j++) g_row_src[t + j * 256] = -1;
    __syncthreads();
    int wbase = 0;
    #pragma unroll
    for (int i = 0; i < 8; i++) { if (i < w) wbase += wcnt[i]; }
    g_upd_s[t] = s;
    if (cond) {
        long long p = (long long)ptr + (wbase + lpref);
        int idx = (int)(p % M_); if (idx < 0) idx += M_;
        g_row_src[idx] = t;
    }
}

// ---------------- full-coverage memory update --------------------------------
__global__ void update_kernel(const float* __restrict__ mem, const float* __restrict__ mom,
                              const float* __restrict__ scores,
                              float* __restrict__ out_mem, float* __restrict__ out_mom,
                              float* __restrict__ out_sc) {
    int row = blockIdx.x, t = threadIdx.x;
    int i = g_row_src[row];
    size_t o = (size_t)row * D_ + t;
    float mval = mem[o], mo = mom[o];
    if (i >= 0) {
        float diff = g_h[i * D_ + t] - mval;
        float nm = MOM_ * mo + (1.0f - MOM_) * diff;
        out_mem[o] = mval + LR_ * nm;
        out_mom[o] = nm;
    } else {
        out_mem[o] = mval;
        out_mom[o] = mo;
    }
    if (t == 0) out_sc[row] = (i >= 0) ? g_upd_s[i] : scores[row];
}

// ---------------- launch -----------------------------------------------------
extern "C" void kernel_launch(void* const* d_in, const int* in_sizes, int n_in,
                              void* d_out, int out_size) {
    const float* src       = (const float*)d_in[0];
    const float* memory    = (const float*)d_in[1];
    const float* momentum  = (const float*)d_in[2];
    const float* scores    = (const float*)d_in[3];
    const float* in_proj_w = (const float*)d_in[4];
    const float* in_proj_b = (const float*)d_in[5];
    const float* out_w     = (const float*)d_in[6];
    const float* out_b     = (const float*)d_in[7];
    const float* w1        = (const float*)d_in[8];
    const float* b1        = (const float*)d_in[9];
    const float* w2        = (const float*)d_in[10];
    const float* b2        = (const float*)d_in[11];
    const float* g1        = (const float*)d_in[12];
    const float* be1       = (const float*)d_in[13];
    const float* g2        = (const float*)d_in[14];
    const float* be2       = (const float*)d_in[15];
    const int*   ptr       = (const int*)d_in[16];

    float* out     = (float*)d_out;
    float* out_mem = out + B_ * D_;
    float* out_mom = out_mem + M_ * D_;
    float* out_sc  = out_mom + M_ * D_;

    float *proj_p, *kv_p, *log_p, *pself_p, *part_p, *ap_p, *fp_p, *ctx_p, *h_p, *hid_p;
    cudaGetSymbolAddress((void**)&proj_p,  g_proj_src);
    cudaGetSymbolAddress((void**)&kv_p,    g_kv_mem);
    cudaGetSymbolAddress((void**)&log_p,   g_logits);
    cudaGetSymbolAddress((void**)&pself_p, g_pself);
    cudaGetSymbolAddress((void**)&part_p,  g_ctx_part);
    cudaGetSymbolAddress((void**)&ap_p,    g_attn_part);
    cudaGetSymbolAddress((void**)&fp_p,    g_ff_part);
    cudaGetSymbolAddress((void**)&ctx_p,   g_ctx);
    cudaGetSymbolAddress((void**)&h_p,     g_h);
    cudaGetSymbolAddress((void**)&hid_p,   g_hidden);

    static cudaStream_t s1 = nullptr, s2 = nullptr;
    static cudaEvent_t eFork = nullptr, eKV = nullptr, eS2 = nullptr,
                       eLN1 = nullptr, eUpd = nullptr;
    if (!s1) {
        cudaStreamCreateWithFlags(&s1, cudaStreamNonBlocking);
        cudaStreamCreateWithFlags(&s2, cudaStreamNonBlocking);
        cudaEventCreateWithFlags(&eFork, cudaEventDisableTiming);
        cudaEventCreateWithFlags(&eKV,   cudaEventDisableTiming);
        cudaEventCreateWithFlags(&eS2,   cudaEventDisableTiming);
        cudaEventCreateWithFlags(&eLN1,  cudaEventDisableTiming);
        cudaEventCreateWithFlags(&eUpd,  cudaEventDisableTiming);
    }

    // ---- fork ----
    cudaEventRecord(eFork, 0);
    cudaStreamWaitEvent(s1, eFork, 0);
    cudaStreamWaitEvent(s2, eFork, 0);

    // S1: memory k|v projection [2048,512] (tf32)
    tmma64<0><<<dim3(8, 32, 1), 128, 0, s1>>>(memory, in_proj_w + D_ * D_, in_proj_b + D_, kv_p,
                                              256, 256, 256, 512, 0, 0, 0);
    cudaEventRecord(eKV, s1);

    // S2: norms -> cosine blockmax (fp32, threshold-sensitive) -> scatter prep
    norms_kernel<<<(B_ + M_ + 7) / 8, dim3(32, 8), 0, s2>>>(src, memory);
    sgemm_cos<<<dim3(32, 4, 1), 128, 0, s2>>>(src, memory, 256, 256, 256);
    scatter_prep_kernel<<<1, 256, 0, s2>>>(ptr);
    cudaEventRecord(eS2, s2);

    // S0: src projections [256,768] (tf32)
    tmma64<0><<<dim3(12, 4, 1), 128>>>(src, in_proj_w, in_proj_b, proj_p,
                                       256, 256, 256, 768, 0, 0, 0);

    // S0: attention chain
    cudaStreamWaitEvent(0, eKV, 0);
    tmma64<0><<<dim3(32, 4, H_), 128>>>(proj_p, kv_p, nullptr, log_p,
                                        32, 768, 512, 2048, 32, 32, B_ * M_);
    softmax_kernel<<<H_ * B_, 256>>>(log_p, proj_p, pself_p);
    av_kernel<<<dim3(2, NSPLIT_, H_), 128>>>(log_p, kv_p, part_p);
    reduce_ctx_kernel<<<B_, 256>>>(part_p, pself_p, proj_p, ctx_p);

    // out-proj split-K x4 (tf32) -> partials; LN1 fuses reduce + bias
    tmma64<0><<<dim3(4, 4, 4), 128>>>(ctx_p, out_w, nullptr, ap_p,
                                      64, 256, 256, 256, 64, 64, B_ * D_);
    ln_split_kernel<<<B_ / 8, 256>>>(src, ap_p, 4, out_b, g1, be1, h_p);
    cudaEventRecord(eLN1, 0);

    // S1: memory update path (needs h + scatter map), overlaps FFN
    cudaStreamWaitEvent(s1, eLN1, 0);
    cudaStreamWaitEvent(s1, eS2, 0);
    update_kernel<<<M_, 256, 0, s1>>>(memory, momentum, scores, out_mem, out_mom, out_sc);
    cudaEventRecord(eUpd, s1);

    // S0: FFN1 (tf32 relu+bias), FFN2 split-K x16 (tf32); LN2 fuses reduce
    tmma64<2><<<dim3(16, 4, 1), 128>>>(h_p, w1, b1, hid_p,
                                       256, 256, 256, 1024, 0, 0, 0);
    tmma64<0><<<dim3(4, 4, FSPLIT_), 128>>>(hid_p, w2, nullptr, fp_p,
                                            1024 / FSPLIT_, 1024, 1024, 256,
                                            1024 / FSPLIT_, 1024 / FSPLIT_, B_ * D_);
    ln_split_kernel<<<B_ / 8, 256>>>(h_p, fp_p, FSPLIT_, b2, g2, be2, out);

    // ---- join ----
    cudaStreamWaitEvent(0, eUpd, 0);
}

// round 7
// speedup vs baseline: 1.1958x; 1.0027x over previous
#include <cuda_runtime.h>
#include <math.h>
#include <stdint.h>

#define B_   256
#define D_   256
#define H_   8
#define HD_  32
#define FF_  1024
#define M_   2048
#define SCALE_ 0.17677669529663687f   /* 1/sqrt(32) */
#define THR_ 0.5f
#define MOM_ 0.9f
#define LR_  0.1f
#define NSPLIT_ 16
#define KSPLIT_ (M_ / NSPLIT_)   /* 128 keys per split */
#define FSPLIT_ 16               /* FFN2 split-K */

// ---------------- scratch (device globals) -----------------------------------
__device__ float g_proj_src[B_ * 3 * D_];
__device__ float g_kv_mem[M_ * 2 * D_];
__device__ float g_logits[H_ * B_ * M_];
__device__ float g_pself[H_ * B_];
__device__ float g_ctx_part[NSPLIT_ * B_ * D_];
__device__ float g_attn_part[4 * B_ * D_];
__device__ float g_ff_part[FSPLIT_ * B_ * D_];
__device__ float g_src_norm[B_];
__device__ float g_mem_norm[M_];
__device__ int   g_flag;
__device__ int   g_max_bits[B_];
__device__ float g_ctx[B_ * D_];
__device__ float g_h[B_ * D_];
__device__ float g_hidden[B_ * FF_];
__device__ int   g_row_src[M_];
__device__ float g_upd_s[B_];

__device__ __forceinline__ uint32_t f2tf32(float f) {
    uint32_t r;
    asm("cvt.rna.tf32.f32 %0, %1;" : "=r"(r) : "f"(f));
    return r;
}
__device__ __forceinline__ void split_tf32(float f, uint32_t& hi, uint32_t& lo) {
    hi = f2tf32(f);
    lo = f2tf32(f - __uint_as_float(hi));
}
__device__ __forceinline__ void mma_tf32(float c[4], const uint32_t a[4], const uint32_t b[2]) {
    asm volatile(
        "mma.sync.aligned.m16n8k8.row.col.f32.tf32.tf32.f32 "
        "{%0,%1,%2,%3}, {%4,%5,%6,%7}, {%8,%9}, {%0,%1,%2,%3};"
        : "+f"(c[0]), "+f"(c[1]), "+f"(c[2]), "+f"(c[3])
        : "r"(a[0]), "r"(a[1]), "r"(a[2]), "r"(a[3]), "r"(b[0]), "r"(b[1]));
}
__device__ __forceinline__ int   fenc(float f) { int i = __float_as_int(f); return i >= 0 ? i : (i ^ 0x7FFFFFFF); }
__device__ __forceinline__ float fdec(int i)   { return __int_as_float(i >= 0 ? i : (i ^ 0x7FFFFFFF)); }

// ---------------- init (S2) ---------------------------------------------------
__global__ void init_kernel() {
    int t = threadIdx.x;
    if (t < B_) g_max_bits[t] = fenc(-1e30f);
    if (t == 0) g_flag = 0;
}

// ---------------- row norms + nonzero flag ------------------------------------
__global__ void norms_kernel(const float* __restrict__ src, const float* __restrict__ mem) {
    int row = blockIdx.x * 8 + threadIdx.y;
    int lane = threadIdx.x;
    if (row >= B_ + M_) return;
    bool is_src = row < B_;
    const float* base = is_src ? (src + row * D_) : (mem + (row - B_) * D_);
    float s = 0.f;
    #pragma unroll
    for (int d = lane; d < D_; d += 32) { float v = base[d]; s += v * v; }
    #pragma unroll
    for (int o = 16; o; o >>= 1) s += __shfl_xor_sync(0xFFFFFFFFu, s, o);
    if (lane == 0) {
        float nv = fmaxf(sqrtf(s), 1e-8f);
        if (is_src) g_src_norm[row] = nv;
        else {
            g_mem_norm[row - B_] = nv;
            if (s > 0.f) atomicOr(&g_flag, 1);
        }
    }
}

// ---------------- TF32 tensor-core GEMM: C[.,N]=A@B^T, 64x64 tile, 128 thr ---
template <int MODE>
__global__ void __launch_bounds__(128)
tmma64(const float* __restrict__ A, const float* __restrict__ Bm,
       const float* __restrict__ bias, float* __restrict__ C,
       int K, int lda, int ldb, int ldc, int aB, int bB, int cB) {
    __shared__ uint32_t As[2][16][72];
    __shared__ uint32_t Bs[2][16][72];
    int tid = threadIdx.x;
    int r = tid & 63, half = tid >> 6;
    int h8 = half * 8;
    const float* Ap = A + (size_t)blockIdx.z * aB + (size_t)(blockIdx.y * 64 + r) * lda + h8;
    const float* Bp = Bm + (size_t)blockIdx.z * bB + (size_t)(blockIdx.x * 64 + r) * ldb + h8;

    float4 a0 = *(const float4*)(Ap);
    float4 a1 = *(const float4*)(Ap + 4);
    float4 b0 = *(const float4*)(Bp);
    float4 b1 = *(const float4*)(Bp + 4);
    As[0][h8 + 0][r] = f2tf32(a0.x); As[0][h8 + 1][r] = f2tf32(a0.y);
    As[0][h8 + 2][r] = f2tf32(a0.z); As[0][h8 + 3][r] = f2tf32(a0.w);
    As[0][h8 + 4][r] = f2tf32(a1.x); As[0][h8 + 5][r] = f2tf32(a1.y);
    As[0][h8 + 6][r] = f2tf32(a1.z); As[0][h8 + 7][r] = f2tf32(a1.w);
    Bs[0][h8 + 0][r] = f2tf32(b0.x); Bs[0][h8 + 1][r] = f2tf32(b0.y);
    Bs[0][h8 + 2][r] = f2tf32(b0.z); Bs[0][h8 + 3][r] = f2tf32(b0.w);
    Bs[0][h8 + 4][r] = f2tf32(b1.x); Bs[0][h8 + 5][r] = f2tf32(b1.y);
    Bs[0][h8 + 6][r] = f2tf32(b1.z); Bs[0][h8 + 7][r] = f2tf32(b1.w);
    __syncthreads();

    int warp = tid >> 5, lane = tid & 31;
    int wm = warp & 1, wn = warp >> 1;
    int lr = lane >> 2, lc = lane & 3;

    float acc[2][4][4];
    #pragma unroll
    for (int mt = 0; mt < 2; mt++)
        #pragma unroll
        for (int nt = 0; nt < 4; nt++)
            #pragma unroll
            for (int q = 0; q < 4; q++) acc[mt][nt][q] = 0.f;

    int nIt = K >> 4;
    for (int it = 0; it < nIt; ++it) {
        int buf = it & 1;
        bool more = (it + 1) < nIt;
        if (more) {
            int k0 = (it + 1) << 4;
            a0 = *(const float4*)(Ap + k0);
            a1 = *(const float4*)(Ap + k0 + 4);
            b0 = *(const float4*)(Bp + k0);
            b1 = *(const float4*)(Bp + k0 + 4);
        }
        #pragma unroll
        for (int k8 = 0; k8 < 16; k8 += 8) {
            uint32_t af[2][4], bf[4][2];
            #pragma unroll
            for (int mt = 0; mt < 2; mt++) {
                int row = wm * 32 + mt * 16 + lr;
                af[mt][0] = As[buf][k8 + lc][row];
                af[mt][1] = As[buf][k8 + lc][row + 8];
                af[mt][2] = As[buf][k8 + lc + 4][row];
                af[mt][3] = As[buf][k8 + lc + 4][row + 8];
            }
            #pragma unroll
            for (int nt = 0; nt < 4; nt++) {
                int col = wn * 32 + nt * 8 + lr;
                bf[nt][0] = Bs[buf][k8 + lc][col];
                bf[nt][1] = Bs[buf][k8 + lc + 4][col];
            }
            #pragma unroll
            for (int mt = 0; mt < 2; mt++)
                #pragma unroll
                for (int nt = 0; nt < 4; nt++) mma_tf32(acc[mt][nt], af[mt], bf[nt]);
        }
        if (more) {
            int nb = buf ^ 1;
            As[nb][h8 + 0][r] = f2tf32(a0.x); As[nb][h8 + 1][r] = f2tf32(a0.y);
            As[nb][h8 + 2][r] = f2tf32(a0.z); As[nb][h8 + 3][r] = f2tf32(a0.w);
            As[nb][h8 + 4][r] = f2tf32(a1.x); As[nb][h8 + 5][r] = f2tf32(a1.y);
            As[nb][h8 + 6][r] = f2tf32(a1.z); As[nb][h8 + 7][r] = f2tf32(a1.w);
            Bs[nb][h8 + 0][r] = f2tf32(b0.x); Bs[nb][h8 + 1][r] = f2tf32(b0.y);
            Bs[nb][h8 + 2][r] = f2tf32(b0.z); Bs[nb][h8 + 3][r] = f2tf32(b0.w);
            Bs[nb][h8 + 4][r] = f2tf32(b1.x); Bs[nb][h8 + 5][r] = f2tf32(b1.y);
            Bs[nb][h8 + 6][r] = f2tf32(b1.z); Bs[nb][h8 + 7][r] = f2tf32(b1.w);
            __syncthreads();
        }
    }

    float* Cb = C + (size_t)blockIdx.z * cB;
    #pragma unroll
    for (int mt = 0; mt < 2; mt++) {
        #pragma unroll
        for (int nt = 0; nt < 4; nt++) {
            int col_g = blockIdx.x * 64 + wn * 32 + nt * 8 + 2 * lc;
            float bj0 = bias ? bias[col_g] : 0.f;
            float bj1 = bias ? bias[col_g + 1] : 0.f;
            #pragma unroll
            for (int hrow = 0; hrow < 2; hrow++) {
                int row_g = blockIdx.y * 64 + wm * 32 + mt * 16 + lr + hrow * 8;
                float v0 = acc[mt][nt][hrow * 2 + 0] + bj0;
                float v1 = acc[mt][nt][hrow * 2 + 1] + bj1;
                if (MODE == 2) { v0 = fmaxf(v0, 0.f); v1 = fmaxf(v1, 0.f); }
                *(float2*)&Cb[(size_t)row_g * ldc + col_g] = make_float2(v0, v1);
            }
        }
    }
}

// ---------------- 3xTF32 cosine GEMM: max cos-sim epilogue -> g_max_bits -----
__global__ void __launch_bounds__(128)
cos_tmma(const float* __restrict__ A, const float* __restrict__ Bm) {
    __shared__ uint32_t Ah[2][16][72], Al[2][16][72];
    __shared__ uint32_t Bh[2][16][72], Bl[2][16][72];
    int tid = threadIdx.x;
    int r = tid & 63, half = tid >> 6;
    int h8 = half * 8;
    const float* Ap = A + (size_t)(blockIdx.y * 64 + r) * D_ + h8;
    const float* Bp = Bm + (size_t)(blockIdx.x * 64 + r) * D_ + h8;

    float av[8], bv[8];
    *(float4*)&av[0] = *(const float4*)(Ap);
    *(float4*)&av[4] = *(const float4*)(Ap + 4);
    *(float4*)&bv[0] = *(const float4*)(Bp);
    *(float4*)&bv[4] = *(const float4*)(Bp + 4);
    #pragma unroll
    for (int q = 0; q < 8; q++) {
        split_tf32(av[q], Ah[0][h8 + q][r], Al[0][h8 + q][r]);
        split_tf32(bv[q], Bh[0][h8 + q][r], Bl[0][h8 + q][r]);
    }
    __syncthreads();

    int warp = tid >> 5, lane = tid & 31;
    int wm = warp & 1, wn = warp >> 1;
    int lr = lane >> 2, lc = lane & 3;

    float acc[2][4][4];
    #pragma unroll
    for (int mt = 0; mt < 2; mt++)
        #pragma unroll
        for (int nt = 0; nt < 4; nt++)
            #pragma unroll
            for (int q = 0; q < 4; q++) acc[mt][nt][q] = 0.f;

    const int nIt = D_ >> 4;   // 16
    for (int it = 0; it < nIt; ++it) {
        int buf = it & 1;
        bool more = (it + 1) < nIt;
        if (more) {
            int k0 = (it + 1) << 4;
            *(float4*)&av[0] = *(const float4*)(Ap + k0);
            *(float4*)&av[4] = *(const float4*)(Ap + k0 + 4);
            *(float4*)&bv[0] = *(const float4*)(Bp + k0);
            *(float4*)&bv[4] = *(const float4*)(Bp + k0 + 4);
        }
        #pragma unroll
        for (int k8 = 0; k8 < 16; k8 += 8) {
            uint32_t ah[2][4], al[2][4], bh[4][2], bl[4][2];
            #pragma unroll
            for (int mt = 0; mt < 2; mt++) {
                int row = wm * 32 + mt * 16 + lr;
                ah[mt][0] = Ah[buf][k8 + lc][row];     al[mt][0] = Al[buf][k8 + lc][row];
                ah[mt][1] = Ah[buf][k8 + lc][row + 8]; al[mt][1] = Al[buf][k8 + lc][row + 8];
                ah[mt][2] = Ah[buf][k8 + lc + 4][row]; al[mt][2] = Al[buf][k8 + lc + 4][row];
                ah[mt][3] = Ah[buf][k8 + lc + 4][row + 8]; al[mt][3] = Al[buf][k8 + lc + 4][row + 8];
            }
            #pragma unroll
            for (int nt = 0; nt < 4; nt++) {
                int col = wn * 32 + nt * 8 + lr;
                bh[nt][0] = Bh[buf][k8 + lc][col];     bl[nt][0] = Bl[buf][k8 + lc][col];
                bh[nt][1] = Bh[buf][k8 + lc + 4][col]; bl[nt][1] = Bl[buf][k8 + lc + 4][col];
            }
            #pragma unroll
            for (int mt = 0; mt < 2; mt++)
                #pragma unroll
                for (int nt = 0; nt < 4; nt++) {
                    mma_tf32(acc[mt][nt], ah[mt], bh[nt]);
                    mma_tf32(acc[mt][nt], ah[mt], bl[nt]);
                    mma_tf32(acc[mt][nt], al[mt], bh[nt]);
                }
        }
        if (more) {
            int nb = buf ^ 1;
            #pragma unroll
            for (int q = 0; q < 8; q++) {
                split_tf32(av[q], Ah[nb][h8 + q][r], Al[nb][h8 + q][r]);
                split_tf32(bv[q], Bh[nb][h8 + q][r], Bl[nb][h8 + q][r]);
            }
            __syncthreads();
        }
    }

    int row_base = blockIdx.y * 64, col_base = blockIdx.x * 64;
    float inm[4][2];
    #pragma unroll
    for (int nt = 0; nt < 4; nt++) {
        int col = col_base + wn * 32 + nt * 8 + 2 * lc;
        inm[nt][0] = 1.f / g_mem_norm[col];
        inm[nt][1] = 1.f / g_mem_norm[col + 1];
    }
    #pragma unroll
    for (int mt = 0; mt < 2; mt++) {
        #pragma unroll
        for (int hrow = 0; hrow < 2; hrow++) {
            int rl = wm * 32 + mt * 16 + lr + hrow * 8;
            float ins = 1.f / g_src_norm[row_base + rl];
            float mx = -1e30f;
            #pragma unroll
            for (int nt = 0; nt < 4; nt++) {
                mx = fmaxf(mx, acc[mt][nt][hrow * 2 + 0] * inm[nt][0]);
                mx = fmaxf(mx, acc[mt][nt][hrow * 2 + 1] * inm[nt][1]);
            }
            mx *= ins;
            mx = fmaxf(mx, __shfl_xor_sync(0xFFFFFFFFu, mx, 1));
            mx = fmaxf(mx, __shfl_xor_sync(0xFFFFFFFFu, mx, 2));
            if (lc == 0) atomicMax(&g_max_bits[row_base + rl], fenc(mx));
        }
    }
}

// ---------------- softmax over [M logits + self], normalized in place --------
__global__ void softmax_kernel(float* __restrict__ logits, const float* __restrict__ projsrc,
                               float* __restrict__ pself) {
    int h = blockIdx.x >> 8, b = blockIdx.x & 255;
    int tid = threadIdx.x, w = tid >> 5, lane = tid & 31;
    float* row = logits + ((size_t)(h * B_ + b)) * M_;

    __shared__ float s_ls, smax[8], ssum[8];
    if (tid < 32) {
        float q = projsrc[b * 768 + h * 32 + tid];
        float k = projsrc[b * 768 + 256 + h * 32 + tid];
        float d = q * k;
        #pragma unroll
        for (int o = 16; o; o >>= 1) d += __shfl_xor_sync(0xFFFFFFFFu, d, o);
        if (tid == 0) s_ls = d * SCALE_;
    }
    float4 v0 = ((const float4*)row)[tid * 2];
    float4 v1 = ((const float4*)row)[tid * 2 + 1];
    float x[8] = {v0.x, v0.y, v0.z, v0.w, v1.x, v1.y, v1.z, v1.w};
    float lmax = -1e30f;
    #pragma unroll
    for (int j = 0; j < 8; j++) { x[j] *= SCALE_; lmax = fmaxf(lmax, x[j]); }
    #pragma unroll
    for (int o = 16; o; o >>= 1) lmax = fmaxf(lmax, __shfl_xor_sync(0xFFFFFFFFu, lmax, o));
    if (lane == 0) smax[w] = lmax;
    __syncthreads();
    float gmax = s_ls;
    #pragma unroll
    for (int i = 0; i < 8; i++) gmax = fmaxf(gmax, smax[i]);
    float lsum = 0.f;
    #pragma unroll
    for (int j = 0; j < 8; j++) { x[j] = __expf(x[j] - gmax); lsum += x[j]; }
    #pragma unroll
    for (int o = 16; o; o >>= 1) lsum += __shfl_xor_sync(0xFFFFFFFFu, lsum, o);
    if (lane == 0) ssum[w] = lsum;
    __syncthreads();
    float eself = __expf(s_ls - gmax);
    float tot = eself;
    #pragma unroll
    for (int i = 0; i < 8; i++) tot += ssum[i];
    float inv = 1.f / tot;
    #pragma unroll
    for (int j = 0; j < 8; j++) x[j] *= inv;
    ((float4*)row)[tid * 2]     = make_float4(x[0], x[1], x[2], x[3]);
    ((float4*)row)[tid * 2 + 1] = make_float4(x[4], x[5], x[6], x[7]);
    if (tid == 0) pself[h * B_ + b] = eself * inv;
}

// ---------------- AV split-K on tensor cores (tf32) ---------------------------
// grid (qb=2, split=16, h=8), 128 thr; tile 128 q-rows x 32 v-dims, K=128.
__global__ void __launch_bounds__(128)
av_tmma(const float* __restrict__ probs, const float* __restrict__ kv,
        float* __restrict__ part) {
    __shared__ uint32_t Ps[2][16][132];
    __shared__ uint32_t Vs[2][16][40];
    int tid = threadIdx.x;
    int qb = blockIdx.x, split = blockIdx.y, h = blockIdx.z;

    const float* Prow = probs + ((size_t)(h * B_ + qb * 128 + tid)) * M_ + split * KSPLIT_;
    int vr = tid >> 3, vc = (tid & 7) * 4;
    const float* Vbase = kv + 256 + h * 32 + vc;

    float pv[16]; float4 vv;
    *(float4*)&pv[0]  = *(const float4*)(Prow);
    *(float4*)&pv[4]  = *(const float4*)(Prow + 4);
    *(float4*)&pv[8]  = *(const float4*)(Prow + 8);
    *(float4*)&pv[12] = *(const float4*)(Prow + 12);
    vv = *(const float4*)(Vbase + (size_t)(split * KSPLIT_ + vr) * 512);
    #pragma unroll
    for (int q = 0; q < 16; q++) Ps[0][q][tid] = f2tf32(pv[q]);
    Vs[0][vr][vc + 0] = f2tf32(vv.x); Vs[0][vr][vc + 1] = f2tf32(vv.y);
    Vs[0][vr][vc + 2] = f2tf32(vv.z); Vs[0][vr][vc + 3] = f2tf32(vv.w);
    __syncthreads();

    int warp = tid >> 5, lane = tid & 31;
    int lr = lane >> 2, lc = lane & 3;

    float acc[2][4][4];
    #pragma unroll
    for (int mt = 0; mt < 2; mt++)
        #pragma unroll
        for (int nt = 0; nt < 4; nt++)
            #pragma unroll
            for (int q = 0; q < 4; q++) acc[mt][nt][q] = 0.f;

    const int nIt = KSPLIT_ / 16;   // 8
    for (int it = 0; it < nIt; ++it) {
        int buf = it & 1;
        bool more = (it + 1) < nIt;
        if (more) {
            int k0 = (it + 1) * 16;
            *(float4*)&pv[0]  = *(const float4*)(Prow + k0);
            *(float4*)&pv[4]  = *(const float4*)(Prow + k0 + 4);
            *(float4*)&pv[8]  = *(const float4*)(Prow + k0 + 8);
            *(float4*)&pv[12] = *(const float4*)(Prow + k0 + 12);
            vv = *(const float4*)(Vbase + (size_t)(split * KSPLIT_ + k0 + vr) * 512);
        }
        #pragma unroll
        for (int k8 = 0; k8 < 16; k8 += 8) {
            uint32_t af[2][4], bf[4][2];
            #pragma unroll
            for (int mt = 0; mt < 2; mt++) {
                int row = warp * 32 + mt * 16 + lr;
                af[mt][0] = Ps[buf][k8 + lc][row];
                af[mt][1] = Ps[buf][k8 + lc][row + 8];
                af[mt][2] = Ps[buf][k8 + lc + 4][row];
                af[mt][3] = Ps[buf][k8 + lc + 4][row + 8];
            }
            #pragma unroll
            for (int nt = 0; nt < 4; nt++) {
                int col = nt * 8 + lr;
                bf[nt][0] = Vs[buf][k8 + lc][col];
                bf[nt][1] = Vs[buf][k8 + lc + 4][col];
            }
            #pragma unroll
            for (int mt = 0; mt < 2; mt++)
                #pragma unroll
                for (int nt = 0; nt < 4; nt++) mma_tf32(acc[mt][nt], af[mt], bf[nt]);
        }
        if (more) {
            int nb = buf ^ 1;
            #pragma unroll
            for (int q = 0; q < 16; q++) Ps[nb][q][tid] = f2tf32(pv[q]);
            Vs[nb][vr][vc + 0] = f2tf32(vv.x); Vs[nb][vr][vc + 1] = f2tf32(vv.y);
            Vs[nb][vr][vc + 2] = f2tf32(vv.z); Vs[nb][vr][vc + 3] = f2tf32(vv.w);
            __syncthreads();
        }
    }

    float* Pb = part + (size_t)split * (B_ * D_);
    #pragma unroll
    for (int mt = 0; mt < 2; mt++) {
        #pragma unroll
        for (int nt = 0; nt < 4; nt++) {
            int col = nt * 8 + 2 * lc;
            #pragma unroll
            for (int hrow = 0; hrow < 2; hrow++) {
                int row_g = qb * 128 + warp * 32 + mt * 16 + lr + hrow * 8;
                *(float2*)&Pb[(size_t)row_g * D_ + h * 32 + col]
                    = make_float2(acc[mt][nt][hrow * 2 + 0], acc[mt][nt][hrow * 2 + 1]);
            }
        }
    }
}

// ---------------- reduce AV partials + self term -> ctx ----------------------
__global__ void reduce_ctx_kernel(const float* __restrict__ part, const float* __restrict__ pself,
                                  const float* __restrict__ projsrc, float* __restrict__ ctx) {
    int b = blockIdx.x, d = threadIdx.x;
    int h = d >> 5;
    float s = 0.f;
    #pragma unroll
    for (int sp = 0; sp < NSPLIT_; sp++) s += part[(size_t)sp * (B_ * D_) + b * D_ + d];
    s += pself[h * B_ + b] * projsrc[b * 768 + 512 + d];
    ctx[b * D_ + d] = s;
}

// ---------------- LN with fused split-K reduce -------------------------------
__global__ void ln_split_kernel(const float* __restrict__ a, const float* __restrict__ part,
                                int nsplit, const float* __restrict__ bias,
                                const float* __restrict__ g, const float* __restrict__ be,
                                float* __restrict__ out) {
    int w = threadIdx.x >> 5, lane = threadIdx.x & 31;
    int row = blockIdx.x * 8 + w;
    size_t base = (size_t)row * D_ + lane * 8;
    float4 a0 = *(const float4*)(a + base);
    float4 a1 = *(const float4*)(a + base + 4);
    float x[8] = {a0.x, a0.y, a0.z, a0.w, a1.x, a1.y, a1.z, a1.w};
    for (int z = 0; z < nsplit; z++) {
        const float* pp = part + (size_t)z * (B_ * D_) + base;
        float4 p0 = *(const float4*)pp;
        float4 p1 = *(const float4*)(pp + 4);
        x[0]+=p0.x; x[1]+=p0.y; x[2]+=p0.z; x[3]+=p0.w;
        x[4]+=p1.x; x[5]+=p1.y; x[6]+=p1.z; x[7]+=p1.w;
    }
    float4 bb0 = *(const float4*)(bias + lane * 8);
    float4 bb1 = *(const float4*)(bias + lane * 8 + 4);
    x[0]+=bb0.x; x[1]+=bb0.y; x[2]+=bb0.z; x[3]+=bb0.w;
    x[4]+=bb1.x; x[5]+=bb1.y; x[6]+=bb1.z; x[7]+=bb1.w;

    float s = 0.f;
    #pragma unroll
    for (int j = 0; j < 8; j++) s += x[j];
    #pragma unroll
    for (int o = 16; o; o >>= 1) s += __shfl_xor_sync(0xFFFFFFFFu, s, o);
    float mean = s * (1.f / D_);
    float v = 0.f;
    #pragma unroll
    for (int j = 0; j < 8; j++) { float c = x[j] - mean; v += c * c; }
    #pragma unroll
    for (int o = 16; o; o >>= 1) v += __shfl_xor_sync(0xFFFFFFFFu, v, o);
    float rstd = rsqrtf(v * (1.f / D_) + 1e-5f);
    float4 g0 = *(const float4*)(g + lane * 8);
    float4 g1 = *(const float4*)(g + lane * 8 + 4);
    float4 e0 = *(const float4*)(be + lane * 8);
    float4 e1 = *(const float4*)(be + lane * 8 + 4);
    float gg[8] = {g0.x, g0.y, g0.z, g0.w, g1.x, g1.y, g1.z, g1.w};
    float ee[8] = {e0.x, e0.y, e0.z, e0.w, e1.x, e1.y, e1.z, e1.w};
    float o8[8];
    #pragma unroll
    for (int j = 0; j < 8; j++) o8[j] = (x[j] - mean) * rstd * gg[j] + ee[j];
    *(float4*)(out + base)     = make_float4(o8[0], o8[1], o8[2], o8[3]);
    *(float4*)(out + base + 4) = make_float4(o8[4], o8[5], o8[6], o8[7]);
}

// ---------------- scatter prep: ballot-scan prefix ----------------------------
__global__ void scatter_prep_kernel(const int* __restrict__ ptrp) {
    __shared__ int wcnt[8];
    int t = threadIdx.x, w = t >> 5, lane = t & 31;
    int flag = g_flag;
    float s = flag ? (1.0f - fdec(g_max_bits[t])) : 1.0f;
    int ptr = *ptrp;
    long long forced = (long long)M_ - (long long)ptr;
    int cond = (s > THR_) || ((long long)t < forced);
    unsigned mask = __ballot_sync(0xFFFFFFFFu, cond);
    int lpref = __popc(mask & ((1u << lane) - 1u));
    if (lane == 31) wcnt[w] = lpref + cond;
    #pragma unroll
    for (int j = 0; j < 8; j++) g_row_src[t + j * 256] = -1;
    __syncthreads();
    int wbase = 0;
    #pragma unroll
    for (int i = 0; i < 8; i++) { if (i < w) wbase += wcnt[i]; }
    g_upd_s[t] = s;
    if (cond) {
        long long p = (long long)ptr + (wbase + lpref);
        int idx = (int)(p % M_); if (idx < 0) idx += M_;
        g_row_src[idx] = t;
    }
}

// ---------------- full-coverage memory update --------------------------------
__global__ void update_kernel(const float* __restrict__ mem, const float* __restrict__ mom,
                              const float* __restrict__ scores,
                              float* __restrict__ out_mem, float* __restrict__ out_mom,
                              float* __restrict__ out_sc) {
    int row = blockIdx.x, t = threadIdx.x;
    int i = g_row_src[row];
    size_t o = (size_t)row * D_ + t;
    float mval = mem[o], mo = mom[o];
    if (i >= 0) {
        float diff = g_h[i * D_ + t] - mval;
        float nm = MOM_ * mo + (1.0f - MOM_) * diff;
        out_mem[o] = mval + LR_ * nm;
        out_mom[o] = nm;
    } else {
        out_mem[o] = mval;
        out_mom[o] = mo;
    }
    if (t == 0) out_sc[row] = (i >= 0) ? g_upd_s[i] : scores[row];
}

// ---------------- launch -----------------------------------------------------
extern "C" void kernel_launch(void* const* d_in, const int* in_sizes, int n_in,
                              void* d_out, int out_size) {
    const float* src       = (const float*)d_in[0];
    const float* memory    = (const float*)d_in[1];
    const float* momentum  = (const float*)d_in[2];
    const float* scores    = (const float*)d_in[3];
    const float* in_proj_w = (const float*)d_in[4];
    const float* in_proj_b = (const float*)d_in[5];
    const float* out_w     = (const float*)d_in[6];
    const float* out_b     = (const float*)d_in[7];
    const float* w1        = (const float*)d_in[8];
    const float* b1        = (const float*)d_in[9];
    const float* w2        = (const float*)d_in[10];
    const float* b2        = (const float*)d_in[11];
    const float* g1        = (const float*)d_in[12];
    const float* be1       = (const float*)d_in[13];
    const float* g2        = (const float*)d_in[14];
    const float* be2       = (const float*)d_in[15];
    const int*   ptr       = (const int*)d_in[16];

    float* out     = (float*)d_out;
    float* out_mem = out + B_ * D_;
    float* out_mom = out_mem + M_ * D_;
    float* out_sc  = out_mom + M_ * D_;

    float *proj_p, *kv_p, *log_p, *pself_p, *part_p, *ap_p, *fp_p, *ctx_p, *h_p, *hid_p;
    cudaGetSymbolAddress((void**)&proj_p,  g_proj_src);
    cudaGetSymbolAddress((void**)&kv_p,    g_kv_mem);
    cudaGetSymbolAddress((void**)&log_p,   g_logits);
    cudaGetSymbolAddress((void**)&pself_p, g_pself);
    cudaGetSymbolAddress((void**)&part_p,  g_ctx_part);
    cudaGetSymbolAddress((void**)&ap_p,    g_attn_part);
    cudaGetSymbolAddress((void**)&fp_p,    g_ff_part);
    cudaGetSymbolAddress((void**)&ctx_p,   g_ctx);
    cudaGetSymbolAddress((void**)&h_p,     g_h);
    cudaGetSymbolAddress((void**)&hid_p,   g_hidden);

    static cudaStream_t s1 = nullptr, s2 = nullptr;
    static cudaEvent_t eFork = nullptr, eKV = nullptr, eS2 = nullptr,
                       eLN1 = nullptr, eUpd = nullptr;
    if (!s1) {
        cudaStreamCreateWithFlags(&s1, cudaStreamNonBlocking);
        cudaStreamCreateWithFlags(&s2, cudaStreamNonBlocking);
        cudaEventCreateWithFlags(&eFork, cudaEventDisableTiming);
        cudaEventCreateWithFlags(&eKV,   cudaEventDisableTiming);
        cudaEventCreateWithFlags(&eS2,   cudaEventDisableTiming);
        cudaEventCreateWithFlags(&eLN1,  cudaEventDisableTiming);
        cudaEventCreateWithFlags(&eUpd,  cudaEventDisableTiming);
    }

    // ---- fork ----
    cudaEventRecord(eFork, 0);
    cudaStreamWaitEvent(s1, eFork, 0);
    cudaStreamWaitEvent(s2, eFork, 0);

    // S1: memory k|v projection [2048,512] (tf32)
    tmma64<0><<<dim3(8, 32, 1), 128, 0, s1>>>(memory, in_proj_w + D_ * D_, in_proj_b + D_, kv_p,
                                              256, 256, 256, 512, 0, 0, 0);
    cudaEventRecord(eKV, s1);

    // S2: init -> norms (+flag) -> 3xTF32 cosine -> scatter prep
    init_kernel<<<1, 256, 0, s2>>>();
    norms_kernel<<<(B_ + M_ + 7) / 8, dim3(32, 8), 0, s2>>>(src, memory);
    cos_tmma<<<dim3(32, 4, 1), 128, 0, s2>>>(src, memory);
    scatter_prep_kernel<<<1, 256, 0, s2>>>(ptr);
    cudaEventRecord(eS2, s2);

    // S0: src projections [256,768] (tf32)
    tmma64<0><<<dim3(12, 4, 1), 128>>>(src, in_proj_w, in_proj_b, proj_p,
                                       256, 256, 256, 768, 0, 0, 0);

    // S0: attention chain
    cudaStreamWaitEvent(0, eKV, 0);
    tmma64<0><<<dim3(32, 4, H_), 128>>>(proj_p, kv_p, nullptr, log_p,
                                        32, 768, 512, 2048, 32, 32, B_ * M_);
    softmax_kernel<<<H_ * B_, 256>>>(log_p, proj_p, pself_p);
    av_tmma<<<dim3(2, NSPLIT_, H_), 128>>>(log_p, kv_p, part_p);
    reduce_ctx_kernel<<<B_, 256>>>(part_p, pself_p, proj_p, ctx_p);

    // out-proj split-K x4 (tf32) -> partials; LN1 fuses reduce + bias
    tmma64<0><<<dim3(4, 4, 4), 128>>>(ctx_p, out_w, nullptr, ap_p,
                                      64, 256, 256, 256, 64, 64, B_ * D_);
    ln_split_kernel<<<B_ / 8, 256>>>(src, ap_p, 4, out_b, g1, be1, h_p);
    cudaEventRecord(eLN1, 0);

    // S1: memory update path (needs h + scatter map), overlaps FFN
    cudaStreamWaitEvent(s1, eLN1, 0);
    cudaStreamWaitEvent(s1, eS2, 0);
    update_kernel<<<M_, 256, 0, s1>>>(memory, momentum, scores, out_mem, out_mom, out_sc);
    cudaEventRecord(eUpd, s1);

    // S0: FFN1 (tf32 relu+bias), FFN2 split-K x16 (tf32); LN2 fuses reduce
    tmma64<2><<<dim3(16, 4, 1), 128>>>(h_p, w1, b1, hid_p,
                                       256, 256, 256, 1024, 0, 0, 0);
    tmma64<0><<<dim3(4, 4, FSPLIT_), 128>>>(hid_p, w2, nullptr, fp_p,
                                            1024 / FSPLIT_, 1024, 1024, 256,
                                            1024 / FSPLIT_, 1024 / FSPLIT_, B_ * D_);
    ln_split_kernel<<<B_ / 8, 256>>>(h_p, fp_p, FSPLIT_, b2, g2, be2, out);

    // ---- join ----
    cudaStreamWaitEvent(0, eUpd, 0);
}